// round 15
// baseline (speedup 1.0000x reference)
#include <cuda_runtime.h>
#include <cstdint>

// ====================================================================
// QuantumLayer: 3x (fft2,diag(q),ifft2) == ONE real 32-tap circulant
// along q; pz dead; out[q][d] = |noisy| at d or 63-d,
// flip = px ^ (fid < 0.9). JAX threefry (partitionable) on device.
// R14 == R13 resubmit (container infra failure): R12 + single-phase
//      12-value butterfly reduction (both dots computed
//      unconditionally; px selects post-reduction).
// ====================================================================

static __device__ float        g_ck[32];    // composed circulant kernel
static __device__ float        g_esum[32];  // |sum_a ecc[a][q]|
static __device__ float        g_syn0[32];  // syn[0][q]
static __device__ unsigned int g_keys[4];   // k1 (amp), k2 (phase)

// ---------------- threefry2x32 ----------------
__device__ __forceinline__ unsigned int rotl32(unsigned int x, int r) {
    return __funnelshift_l(x, x, r);
}

__device__ __forceinline__ void tf2x32(unsigned int k0, unsigned int k1,
                                       unsigned int x0, unsigned int x1,
                                       unsigned int& o0, unsigned int& o1) {
    unsigned int k2 = k0 ^ k1 ^ 0x1BD11BDAu;
    x0 += k0; x1 += k1;
#define TFR4(a,b,c,d) \
    x0 += x1; x1 = rotl32(x1,(a)) ^ x0; \
    x0 += x1; x1 = rotl32(x1,(b)) ^ x0; \
    x0 += x1; x1 = rotl32(x1,(c)) ^ x0; \
    x0 += x1; x1 = rotl32(x1,(d)) ^ x0;
    TFR4(13,15,26, 6)  x0 += k1; x1 += k2 + 1u;
    TFR4(17,29,16,24)  x0 += k2; x1 += k0 + 2u;
    TFR4(13,15,26, 6)  x0 += k0; x1 += k1 + 3u;
    TFR4(17,29,16,24)  x0 += k1; x1 += k2 + 4u;
    TFR4(13,15,26, 6)  x0 += k2; x1 += k0 + 5u;
#undef TFR4
    o0 = x0; o1 = x1;
}

// partitionable random_bits: counter = (hi=0, lo=idx), fold the two outputs
__device__ __forceinline__ unsigned int tf_fold(unsigned int k0, unsigned int k1,
                                                unsigned int idx) {
    unsigned int o0, o1;
    tf2x32(k0, k1, 0u, idx, o0, o1);
    return o0 ^ o1;
}

// bits -> N(0,1), matching jax.random.normal float32 path
__device__ __forceinline__ float nrm_from_bits(unsigned int bits) {
    float f = __uint_as_float(0x3f800000u | (bits >> 9)) - 1.0f; // [0,1)
    const float LO = -0.99999994f;          // nextafter(-1,0) in f32
    float u = fmaxf(LO, fmaf(f, 2.0f, LO)); // (1 - LO) rounds to exactly 2.0f
    return 1.41421354f * erfinvf(u);
}

// ---------------- setup: QR -> thetas -> circulant, keys, scalars ----
__global__ void qsetup(const float* __restrict__ rx, const float* __restrict__ ry,
                       const float* __restrict__ rz, const float* __restrict__ ecc,
                       const float* __restrict__ syn) {
    __shared__ double sA0[256], sA1[256], sV[256], sW[256], sT2[256];
    __shared__ double red[256];
    __shared__ double sTh[3][32];
    __shared__ double sCax[3][32], sT12[32];
    __shared__ double cw[32], sw[32];
    __shared__ double dreS[32], dimS[32];
    __shared__ double sc_tau, sc_sc, sc_tau2, sc_sc2, sc_tva, sc_tvu;

    const int tid = threadIdx.x;
    const float* ps[3] = { rx, ry, rz };

    auto blkred = [&](double v) -> double {
        red[tid] = v; __syncthreads();
        for (int o = 128; o > 0; o >>= 1) {
            if (tid < o) red[tid] += red[tid + o];
            __syncthreads();
        }
        double r = red[0]; __syncthreads();
        return r;
    };

    for (int a = 0; a < 3; ++a) {
        const float* p = ps[a];
        sA0[tid] = (double)p[2*tid];
        sA1[tid] = (double)p[2*tid + 1];
        __syncthreads();

        double na = sqrt(blkred(sA0[tid] * sA0[tid]));
        if (tid == 0) {
            double alpha = sA0[0];
            double beta  = (alpha >= 0.0) ? -na : na;     // LAPACK slarfg sign
            sc_tau = (beta - alpha) / beta;
            sc_sc  = 1.0 / (alpha - beta);
        }
        __syncthreads();
        sV[tid] = (tid == 0) ? 1.0 : sA0[tid] * sc_sc;
        __syncthreads();

        double va = blkred(sV[tid] * sA1[tid]);
        if (tid == 0) sc_tva = sc_tau * va;
        __syncthreads();
        sW[tid] = sA1[tid] - sc_tva * sV[tid];
        __syncthreads();

        double nz = sqrt(blkred((tid >= 1) ? sW[tid] * sW[tid] : 0.0));
        if (tid == 0) {
            double alpha2 = sW[1];
            double beta2  = (alpha2 >= 0.0) ? -nz : nz;
            sc_tau2 = (beta2 - alpha2) / beta2;
            sc_sc2  = 1.0 / (alpha2 - beta2);
        }
        __syncthreads();
        {
            double u = (tid == 0) ? 0.0 : ((tid == 1) ? 1.0 : sW[tid] * sc_sc2);
            sT2[tid] = ((tid == 1) ? 1.0 : 0.0) - sc_tau2 * u;
        }
        __syncthreads();

        double vu = blkred(sV[tid] * sT2[tid]);
        if (tid == 0) sc_tvu = sc_tau * vu;
        __syncthreads();

        if (tid < 32) {
            double t = 0.0;
            for (int i = 8*tid; i < 8*tid + 8; ++i) {
                double q0 = ((i == 0) ? 1.0 : 0.0) - sc_tau * sV[i];    // Q col 0
                double q1 = sT2[i] - sc_tvu * sV[i];                    // Q col 1
                t += q0 + q1;
            }
            sTh[a][tid] = t / 16.0;
        }
        __syncthreads();
    }

    const double PI = 3.14159265358979323846;
    if (tid < 32) {
        double wv = (2.0 * PI / 32.0) * (double)tid;
        cw[tid] = cos(wv);
        sw[tid] = sin(wv);
    }
    __syncthreads();

    for (int a = 0; a < 3; ++a) {
        if (tid < 32) {
            double ang = 0.5 * sTh[a][2*(tid >> 1)];   // theta[0::2] repeated
            dreS[tid] = cos(ang);
            dimS[tid] = (a < 2) ? 0.0 : ((tid & 1) ? sin(ang) : -sin(ang));
        }
        __syncthreads();
        if (tid < 32) {
            int j = tid;
            double acc = 0.0;
            for (int k = 0; k < 32; ++k) {
                int w = (k * j) & 31;
                acc += dreS[k] * cw[w] - dimS[k] * sw[w];
            }
            sCax[a][j] = acc / 32.0;
        }
        __syncthreads();
    }

    if (tid < 32) {
        double s3 = 0.0;
        for (int m = 0; m < 32; ++m) s3 += sCax[0][m] * sCax[1][(tid - m) & 31];
        sT12[tid] = s3;
    }
    __syncthreads();
    if (tid < 32) {
        double s3 = 0.0;
        for (int m = 0; m < 32; ++m) s3 += sT12[m] * sCax[2][(tid - m) & 31];
        g_ck[tid] = (float)s3;
        g_esum[tid] = fabsf(ecc[tid] + ecc[32 + tid] + ecc[64 + tid]);
        g_syn0[tid] = syn[tid];
    }

    if (tid == 0) {
        unsigned int o0, o1;
        tf2x32(0u, 42u, 0u, 0u, o0, o1); g_keys[0] = o0; g_keys[1] = o1;
        tf2x32(0u, 42u, 0u, 1u, o0, o1); g_keys[2] = o0; g_keys[3] = o1;
    }
}

// ---------------- main: block = (row, q-half); warp w owns 4 q's -----
// 8192 blocks, 128 threads. Block bid: row = bid>>1, half = bid&1.
// Warp w owns q in [16*half + 4*w, 16*half + 4*w + 4).
__global__ __launch_bounds__(128, 8)
void qmain(const float* __restrict__ x, float* __restrict__ out) {
    __shared__ float2 xsh[32][32];       // [m][lane] = (x[m*64+2l], x[m*64+2l+1])
    __shared__ float  s_ct2[64], s_syn[32], s_es[32];
    __shared__ unsigned int s_keys[4];

    const int t = threadIdx.x;
    if (t < 64)               s_ct2[t]      = g_ck[(t + 1) & 31];  // s_ct2[j]=ct[(j+1)&31]
    else if (t < 96)          s_syn[t - 64] = g_syn0[t - 64];
    else                      s_es[t - 96]  = g_esum[t - 96];
    if (t < 4)                s_keys[t]     = g_keys[t];

    const unsigned int row  = blockIdx.x >> 1;
    const int          half = blockIdx.x & 1;

    // load x row (8KB, float4 linear copy == float2[m][lane] layout)
    {
        const float4* xr4 = (const float4*)(x + (size_t)row * 2048);
        float4* xs4 = (float4*)&xsh[0][0];
        #pragma unroll
        for (int i = 0; i < 4; ++i)
            xs4[t + 128 * i] = xr4[t + 128 * i];
    }
    __syncthreads();                     // publishes xsh AND s_keys/tables

    const unsigned int K1a = s_keys[0], K1b = s_keys[1];
    const unsigned int K2a = s_keys[2], K2b = s_keys[3];

    const int warp = t >> 5, lane = t & 31;
    const int qb = half * 16 + warp * 4;             // this warp's 4 q's
    float2* orow2 = (float2*)(out + (size_t)row * 2048);
    const unsigned int idx0 = row * 2048u + 2u * (unsigned int)lane;

    #pragma unroll 1
    for (int qq = 0; qq < 4; qq += 2) {
        const int q = qb + qq;

        // circulant along q for q and q+1 (shared x reads)
        const float* cp = s_ct2 + q + 31;            // cp[-m] = ct[(q-m)&31]
        float sA0 = 0.f, sB0 = 0.f, sA1 = 0.f, sB1 = 0.f;
        #pragma unroll
        for (int m = 0; m < 32; ++m) {
            float2 xm = xsh[m][lane];
            float c0 = cp[-m];
            float c1 = cp[1 - m];
            sA0 = fmaf(c0, xm.x, sA0); sB0 = fmaf(c0, xm.y, sB0);
            sA1 = fmaf(c1, xm.x, sA1); sB1 = fmaf(c1, xm.y, sB1);
        }

        // 8 independent threefry chains (ILP)
        const unsigned int i0 = idx0 + (unsigned int)q * 64u;
        unsigned int bA0a = tf_fold(K1a, K1b, i0);
        unsigned int bA0p = tf_fold(K2a, K2b, i0);
        unsigned int bB0a = tf_fold(K1a, K1b, i0 + 1u);
        unsigned int bB0p = tf_fold(K2a, K2b, i0 + 1u);
        unsigned int bA1a = tf_fold(K1a, K1b, i0 + 64u);
        unsigned int bA1p = tf_fold(K2a, K2b, i0 + 64u);
        unsigned int bB1a = tf_fold(K1a, K1b, i0 + 65u);
        unsigned int bB1p = tf_fold(K2a, K2b, i0 + 65u);

        float ampA0 = 0.01f  * nrm_from_bits(bA0a);
        float phA0  = 0.005f * nrm_from_bits(bA0p);
        float ampB0 = 0.01f  * nrm_from_bits(bB0a);
        float phB0  = 0.005f * nrm_from_bits(bB0p);
        float ampA1 = 0.01f  * nrm_from_bits(bA1a);
        float phA1  = 0.005f * nrm_from_bits(bA1p);
        float ampB1 = 0.01f  * nrm_from_bits(bB1a);
        float phB1  = 0.005f * nrm_from_bits(bB1p);

        float gsA0 = fmaf(ampA0, sA0, sA0), gsB0 = fmaf(ampB0, sB0, sB0);
        float gsA1 = fmaf(ampA1, sA1, sA1), gsB1 = fmaf(ampB1, sB1, sB1);

        // small-angle sincos: |ph| <= 0.027 => err < 3e-8
        float pA0 = phA0 * phA0, pB0 = phB0 * phB0;
        float pA1 = phA1 * phA1, pB1 = phB1 * phB1;
        float cA0 = fmaf(-0.5f, pA0, 1.f), snA0 = phA0 * fmaf(-0.16666667f, pA0, 1.f);
        float cB0 = fmaf(-0.5f, pB0, 1.f), snB0 = phB0 * fmaf(-0.16666667f, pB0, 1.f);
        float cA1 = fmaf(-0.5f, pA1, 1.f), snA1 = phA1 * fmaf(-0.16666667f, pA1, 1.f);
        float cB1 = fmaf(-0.5f, pB1, 1.f), snB1 = phB1 * fmaf(-0.16666667f, pB1, 1.f);

        float reA0 = gsA0 * cA0, imA0 = gsA0 * snA0;
        float reB0 = gsB0 * cB0, imB0 = gsB0 * snB0;
        float reA1 = gsA1 * cA1, imA1 = gsA1 * snA1;
        float reB1 = gsB1 * cB1, imB1 = gsB1 * snB1;

        // flip partners (d<->63-d: lane^31, slot swap) BEFORE reduction
        float sAf0 = __shfl_xor_sync(0xffffffffu, sB0, 31);
        float sBf0 = __shfl_xor_sync(0xffffffffu, sA0, 31);
        float sAf1 = __shfl_xor_sync(0xffffffffu, sB1, 31);
        float sBf1 = __shfl_xor_sync(0xffffffffu, sA1, 31);

        // 12 reduction values, ONE butterfly phase (12-way ILP per level)
        float ns0  = fmaf(gsA0, gsA0, gsB0 * gsB0);
        float ns1  = fmaf(gsA1, gsA1, gsB1 * gsB1);
        float sre0 = reA0 + reB0;
        float sre1 = reA1 + reB1;
        float dNr0 = fmaf(reA0, sA0,  reB0 * sB0);
        float dNi0 = fmaf(imA0, sA0,  imB0 * sB0);
        float dFr0 = fmaf(reA0, sAf0, reB0 * sBf0);
        float dFi0 = fmaf(imA0, sAf0, imB0 * sBf0);
        float dNr1 = fmaf(reA1, sA1,  reB1 * sB1);
        float dNi1 = fmaf(imA1, sA1,  imB1 * sB1);
        float dFr1 = fmaf(reA1, sAf1, reB1 * sBf1);
        float dFi1 = fmaf(imA1, sAf1, imB1 * sBf1);
        #pragma unroll
        for (int o = 16; o > 0; o >>= 1) {
            ns0  += __shfl_xor_sync(0xffffffffu, ns0,  o);
            ns1  += __shfl_xor_sync(0xffffffffu, ns1,  o);
            sre0 += __shfl_xor_sync(0xffffffffu, sre0, o);
            sre1 += __shfl_xor_sync(0xffffffffu, sre1, o);
            dNr0 += __shfl_xor_sync(0xffffffffu, dNr0, o);
            dNi0 += __shfl_xor_sync(0xffffffffu, dNi0, o);
            dFr0 += __shfl_xor_sync(0xffffffffu, dFr0, o);
            dFi0 += __shfl_xor_sync(0xffffffffu, dFi0, o);
            dNr1 += __shfl_xor_sync(0xffffffffu, dNr1, o);
            dNi1 += __shfl_xor_sync(0xffffffffu, dNi1, o);
            dFr1 += __shfl_xor_sync(0xffffffffu, dFr1, o);
            dFi1 += __shfl_xor_sync(0xffffffffu, dFi1, o);
        }

        bool px0 = (s_syn[q]     * sre0) > 0.f;      // warp-uniform
        bool px1 = (s_syn[q + 1] * sre1) > 0.f;
        float dr0 = px0 ? dFr0 : dNr0;
        float di0 = px0 ? dFi0 : dNi0;
        float dr1 = px1 ? dFr1 : dNr1;
        float di1 = px1 ? dFi1 : dNi1;

        float nn0  = sqrtf(ns0) + 1e-8f;
        float nn1  = sqrtf(ns1) + 1e-8f;
        float inv0 = __fdividef(1.f, nn0);
        float inv1 = __fdividef(1.f, nn1);
        float fid0 = s_es[q]     * sqrtf(fmaf(dr0, dr0, di0 * di0)) * inv0;
        float fid1 = s_es[q + 1] * sqrtf(fmaf(dr1, dr1, di1 * di1)) * inv1;
        bool flip0 = px0 != (fid0 < 0.9f);           // warp-uniform
        bool flip1 = px1 != (fid1 < 0.9f);

        float mA0 = fabsf(gsA0), mB0 = fabsf(gsB0);
        float mA1 = fabsf(gsA1), mB1 = fabsf(gsB1);
        float oA0, oB0, oA1, oB1;
        if (flip0) {
            oA0 = __shfl_xor_sync(0xffffffffu, mB0, 31);
            oB0 = __shfl_xor_sync(0xffffffffu, mA0, 31);
        } else { oA0 = mA0; oB0 = mB0; }
        if (flip1) {
            oA1 = __shfl_xor_sync(0xffffffffu, mB1, 31);
            oB1 = __shfl_xor_sync(0xffffffffu, mA1, 31);
        } else { oA1 = mA1; oB1 = mB1; }

        orow2[q * 32 + lane]       = make_float2(oA0 * inv0, oB0 * inv0);
        orow2[(q + 1) * 32 + lane] = make_float2(oA1 * inv1, oB1 * inv1);
    }
}

extern "C" void kernel_launch(void* const* d_in, const int* in_sizes, int n_in,
                              void* d_out, int out_size) {
    const float* x   = (const float*)d_in[0];
    const float* rx  = (const float*)d_in[1];
    const float* ry  = (const float*)d_in[2];
    const float* rz  = (const float*)d_in[3];
    const float* ecc = (const float*)d_in[4];
    const float* syn = (const float*)d_in[5];
    float* out = (float*)d_out;

    qsetup<<<1, 256>>>(rx, ry, rz, ecc, syn);
    qmain<<<4096 * 2, 128>>>(x, out);  // block = (row, q-half); ~6.92 waves
}

// round 16
// speedup vs baseline: 1.0503x; 1.0503x over previous
#include <cuda_runtime.h>
#include <cstdint>

// ====================================================================
// QuantumLayer: 3x (fft2,diag(q),ifft2) == ONE real 32-tap circulant
// along q; pz dead; out[q][d] = |noisy| at d or 63-d,
// flip = px ^ (fid < 0.9). JAX threefry (partitionable) on device.
// R15: R12 reduction structure (measured best) + __launch_bounds__(128,9)
//      occupancy push + parallelized qsetup trig (bit-identical tables).
// ====================================================================

static __device__ float        g_ck[32];    // composed circulant kernel
static __device__ float        g_esum[32];  // |sum_a ecc[a][q]|
static __device__ float        g_syn0[32];  // syn[0][q]
static __device__ unsigned int g_keys[4];   // k1 (amp), k2 (phase)

// ---------------- threefry2x32 ----------------
__device__ __forceinline__ unsigned int rotl32(unsigned int x, int r) {
    return __funnelshift_l(x, x, r);
}

__device__ __forceinline__ void tf2x32(unsigned int k0, unsigned int k1,
                                       unsigned int x0, unsigned int x1,
                                       unsigned int& o0, unsigned int& o1) {
    unsigned int k2 = k0 ^ k1 ^ 0x1BD11BDAu;
    x0 += k0; x1 += k1;
#define TFR4(a,b,c,d) \
    x0 += x1; x1 = rotl32(x1,(a)) ^ x0; \
    x0 += x1; x1 = rotl32(x1,(b)) ^ x0; \
    x0 += x1; x1 = rotl32(x1,(c)) ^ x0; \
    x0 += x1; x1 = rotl32(x1,(d)) ^ x0;
    TFR4(13,15,26, 6)  x0 += k1; x1 += k2 + 1u;
    TFR4(17,29,16,24)  x0 += k2; x1 += k0 + 2u;
    TFR4(13,15,26, 6)  x0 += k0; x1 += k1 + 3u;
    TFR4(17,29,16,24)  x0 += k1; x1 += k2 + 4u;
    TFR4(13,15,26, 6)  x0 += k2; x1 += k0 + 5u;
#undef TFR4
    o0 = x0; o1 = x1;
}

// partitionable random_bits: counter = (hi=0, lo=idx), fold the two outputs
__device__ __forceinline__ unsigned int tf_fold(unsigned int k0, unsigned int k1,
                                                unsigned int idx) {
    unsigned int o0, o1;
    tf2x32(k0, k1, 0u, idx, o0, o1);
    return o0 ^ o1;
}

// bits -> N(0,1), matching jax.random.normal float32 path
__device__ __forceinline__ float nrm_from_bits(unsigned int bits) {
    float f = __uint_as_float(0x3f800000u | (bits >> 9)) - 1.0f; // [0,1)
    const float LO = -0.99999994f;          // nextafter(-1,0) in f32
    float u = fmaxf(LO, fmaf(f, 2.0f, LO)); // (1 - LO) rounds to exactly 2.0f
    return 1.41421354f * erfinvf(u);
}

// ---------------- setup: QR -> thetas -> circulant, keys, scalars ----
__global__ void qsetup(const float* __restrict__ rx, const float* __restrict__ ry,
                       const float* __restrict__ rz, const float* __restrict__ ecc,
                       const float* __restrict__ syn) {
    __shared__ double sA0[256], sA1[256], sV[256], sW[256], sT2[256];
    __shared__ double red[256];
    __shared__ double sTh[3][32];
    __shared__ double sCax[3][32], sT12[32];
    __shared__ double cw[32], sw[32];
    __shared__ double dreS[3][32], dimS[3][32];
    __shared__ double sc_tau, sc_sc, sc_tau2, sc_sc2, sc_tva, sc_tvu;

    const int tid = threadIdx.x;
    const float* ps[3] = { rx, ry, rz };

    auto blkred = [&](double v) -> double {
        red[tid] = v; __syncthreads();
        for (int o = 128; o > 0; o >>= 1) {
            if (tid < o) red[tid] += red[tid + o];
            __syncthreads();
        }
        double r = red[0]; __syncthreads();
        return r;
    };

    for (int a = 0; a < 3; ++a) {
        const float* p = ps[a];
        sA0[tid] = (double)p[2*tid];
        sA1[tid] = (double)p[2*tid + 1];
        __syncthreads();

        double na = sqrt(blkred(sA0[tid] * sA0[tid]));
        if (tid == 0) {
            double alpha = sA0[0];
            double beta  = (alpha >= 0.0) ? -na : na;     // LAPACK slarfg sign
            sc_tau = (beta - alpha) / beta;
            sc_sc  = 1.0 / (alpha - beta);
        }
        __syncthreads();
        sV[tid] = (tid == 0) ? 1.0 : sA0[tid] * sc_sc;
        __syncthreads();

        double va = blkred(sV[tid] * sA1[tid]);
        if (tid == 0) sc_tva = sc_tau * va;
        __syncthreads();
        sW[tid] = sA1[tid] - sc_tva * sV[tid];
        __syncthreads();

        double nz = sqrt(blkred((tid >= 1) ? sW[tid] * sW[tid] : 0.0));
        if (tid == 0) {
            double alpha2 = sW[1];
            double beta2  = (alpha2 >= 0.0) ? -nz : nz;
            sc_tau2 = (beta2 - alpha2) / beta2;
            sc_sc2  = 1.0 / (alpha2 - beta2);
        }
        __syncthreads();
        {
            double u = (tid == 0) ? 0.0 : ((tid == 1) ? 1.0 : sW[tid] * sc_sc2);
            sT2[tid] = ((tid == 1) ? 1.0 : 0.0) - sc_tau2 * u;
        }
        __syncthreads();

        double vu = blkred(sV[tid] * sT2[tid]);
        if (tid == 0) sc_tvu = sc_tau * vu;
        __syncthreads();

        if (tid < 32) {
            double t = 0.0;
            for (int i = 8*tid; i < 8*tid + 8; ++i) {
                double q0 = ((i == 0) ? 1.0 : 0.0) - sc_tau * sV[i];    // Q col 0
                double q1 = sT2[i] - sc_tvu * sV[i];                    // Q col 1
                t += q0 + q1;
            }
            sTh[a][tid] = t / 16.0;
        }
        __syncthreads();
    }

    // roots-of-unity tables + per-axis diag trig, all axes concurrent (96 thr)
    const double PI = 3.14159265358979323846;
    if (tid < 32) {
        double wv = (2.0 * PI / 32.0) * (double)tid;
        cw[tid] = cos(wv);
        sw[tid] = sin(wv);
    }
    if (tid < 96) {
        int a = tid >> 5, k = tid & 31;
        double ang = 0.5 * sTh[a][2*(k >> 1)];     // theta[0::2] repeated
        dreS[a][k] = cos(ang);
        dimS[a][k] = (a < 2) ? 0.0 : ((k & 1) ? sin(ang) : -sin(ang));
    }
    __syncthreads();

    // per-axis circulant kernels, all axes concurrent (96 threads)
    if (tid < 96) {
        int a = tid >> 5, j = tid & 31;
        double acc = 0.0;
        for (int k = 0; k < 32; ++k) {
            int w = (k * j) & 31;
            acc += dreS[a][k] * cw[w] - dimS[a][k] * sw[w];
        }
        sCax[a][j] = acc / 32.0;
    }
    __syncthreads();

    // compose: ct = cx (*) cy (*) cz (circular convolution)
    if (tid < 32) {
        double s3 = 0.0;
        for (int m = 0; m < 32; ++m) s3 += sCax[0][m] * sCax[1][(tid - m) & 31];
        sT12[tid] = s3;
    }
    __syncthreads();
    if (tid < 32) {
        double s3 = 0.0;
        for (int m = 0; m < 32; ++m) s3 += sT12[m] * sCax[2][(tid - m) & 31];
        g_ck[tid] = (float)s3;
        g_esum[tid] = fabsf(ecc[tid] + ecc[32 + tid] + ecc[64 + tid]);
        g_syn0[tid] = syn[tid];
    }

    if (tid == 0) {
        unsigned int o0, o1;
        tf2x32(0u, 42u, 0u, 0u, o0, o1); g_keys[0] = o0; g_keys[1] = o1;
        tf2x32(0u, 42u, 0u, 1u, o0, o1); g_keys[2] = o0; g_keys[3] = o1;
    }
}

// ---------------- main: block = (row, q-half); warp w owns 4 q's -----
// 8192 blocks, 128 threads. Block bid: row = bid>>1, half = bid&1.
// Warp w owns q in [16*half + 4*w, 16*half + 4*w + 4).
__global__ __launch_bounds__(128, 9)
void qmain(const float* __restrict__ x, float* __restrict__ out) {
    __shared__ float2 xsh[32][32];       // [m][lane] = (x[m*64+2l], x[m*64+2l+1])
    __shared__ float  s_ct2[64], s_syn[32], s_es[32];
    __shared__ unsigned int s_keys[4];

    const int t = threadIdx.x;
    if (t < 64)               s_ct2[t]      = g_ck[(t + 1) & 31];  // s_ct2[j]=ct[(j+1)&31]
    else if (t < 96)          s_syn[t - 64] = g_syn0[t - 64];
    else                      s_es[t - 96]  = g_esum[t - 96];
    if (t < 4)                s_keys[t]     = g_keys[t];

    const unsigned int row  = blockIdx.x >> 1;
    const int          half = blockIdx.x & 1;

    // load x row (8KB, float4 linear copy == float2[m][lane] layout)
    {
        const float4* xr4 = (const float4*)(x + (size_t)row * 2048);
        float4* xs4 = (float4*)&xsh[0][0];
        #pragma unroll
        for (int i = 0; i < 4; ++i)
            xs4[t + 128 * i] = xr4[t + 128 * i];
    }
    __syncthreads();                     // publishes xsh AND s_keys/tables

    const unsigned int K1a = s_keys[0], K1b = s_keys[1];
    const unsigned int K2a = s_keys[2], K2b = s_keys[3];

    const int warp = t >> 5, lane = t & 31;
    const int qb = half * 16 + warp * 4;             // this warp's 4 q's
    float2* orow2 = (float2*)(out + (size_t)row * 2048);
    const unsigned int idx0 = row * 2048u + 2u * (unsigned int)lane;

    #pragma unroll 1
    for (int qq = 0; qq < 4; qq += 2) {
        const int q = qb + qq;

        // circulant along q for q and q+1 (shared x reads)
        const float* cp = s_ct2 + q + 31;            // cp[-m] = ct[(q-m)&31]
        float sA0 = 0.f, sB0 = 0.f, sA1 = 0.f, sB1 = 0.f;
        #pragma unroll
        for (int m = 0; m < 32; ++m) {
            float2 xm = xsh[m][lane];
            float c0 = cp[-m];
            float c1 = cp[1 - m];
            sA0 = fmaf(c0, xm.x, sA0); sB0 = fmaf(c0, xm.y, sB0);
            sA1 = fmaf(c1, xm.x, sA1); sB1 = fmaf(c1, xm.y, sB1);
        }

        // 8 independent threefry chains (ILP)
        const unsigned int i0 = idx0 + (unsigned int)q * 64u;
        unsigned int bA0a = tf_fold(K1a, K1b, i0);
        unsigned int bA0p = tf_fold(K2a, K2b, i0);
        unsigned int bB0a = tf_fold(K1a, K1b, i0 + 1u);
        unsigned int bB0p = tf_fold(K2a, K2b, i0 + 1u);
        unsigned int bA1a = tf_fold(K1a, K1b, i0 + 64u);
        unsigned int bA1p = tf_fold(K2a, K2b, i0 + 64u);
        unsigned int bB1a = tf_fold(K1a, K1b, i0 + 65u);
        unsigned int bB1p = tf_fold(K2a, K2b, i0 + 65u);

        float ampA0 = 0.01f  * nrm_from_bits(bA0a);
        float phA0  = 0.005f * nrm_from_bits(bA0p);
        float ampB0 = 0.01f  * nrm_from_bits(bB0a);
        float phB0  = 0.005f * nrm_from_bits(bB0p);
        float ampA1 = 0.01f  * nrm_from_bits(bA1a);
        float phA1  = 0.005f * nrm_from_bits(bA1p);
        float ampB1 = 0.01f  * nrm_from_bits(bB1a);
        float phB1  = 0.005f * nrm_from_bits(bB1p);

        float gsA0 = fmaf(ampA0, sA0, sA0), gsB0 = fmaf(ampB0, sB0, sB0);
        float gsA1 = fmaf(ampA1, sA1, sA1), gsB1 = fmaf(ampB1, sB1, sB1);

        // small-angle sincos: |ph| <= 0.027 => err < 3e-8
        float pA0 = phA0 * phA0, pB0 = phB0 * phB0;
        float pA1 = phA1 * phA1, pB1 = phB1 * phB1;
        float cA0 = fmaf(-0.5f, pA0, 1.f), snA0 = phA0 * fmaf(-0.16666667f, pA0, 1.f);
        float cB0 = fmaf(-0.5f, pB0, 1.f), snB0 = phB0 * fmaf(-0.16666667f, pB0, 1.f);
        float cA1 = fmaf(-0.5f, pA1, 1.f), snA1 = phA1 * fmaf(-0.16666667f, pA1, 1.f);
        float cB1 = fmaf(-0.5f, pB1, 1.f), snB1 = phB1 * fmaf(-0.16666667f, pB1, 1.f);

        float reA0 = gsA0 * cA0, imA0 = gsA0 * snA0;
        float reB0 = gsB0 * cB0, imB0 = gsB0 * snB0;
        float reA1 = gsA1 * cA1, imA1 = gsA1 * snA1;
        float reB1 = gsB1 * cB1, imB1 = gsB1 * snB1;

        // phase 1: norm^2 and Re-sum for both q (interleaved butterflies)
        float ns0  = fmaf(gsA0, gsA0, gsB0 * gsB0);
        float ns1  = fmaf(gsA1, gsA1, gsB1 * gsB1);
        float sre0 = reA0 + reB0;
        float sre1 = reA1 + reB1;
        #pragma unroll
        for (int o = 16; o > 0; o >>= 1) {
            ns0  += __shfl_xor_sync(0xffffffffu, ns0,  o);
            ns1  += __shfl_xor_sync(0xffffffffu, ns1,  o);
            sre0 += __shfl_xor_sync(0xffffffffu, sre0, o);
            sre1 += __shfl_xor_sync(0xffffffffu, sre1, o);
        }
        bool px0 = (s_syn[q]     * sre0) > 0.f;      // warp-uniform
        bool px1 = (s_syn[q + 1] * sre1) > 0.f;

        // phase 2: selected dot only (flip partner d<->63-d: lane^31, slot swap)
        float dr0, di0, dr1, di1;
        if (px0) {
            float sAf = __shfl_xor_sync(0xffffffffu, sB0, 31);
            float sBf = __shfl_xor_sync(0xffffffffu, sA0, 31);
            dr0 = fmaf(reA0, sAf, reB0 * sBf);
            di0 = fmaf(imA0, sAf, imB0 * sBf);
        } else {
            dr0 = fmaf(reA0, sA0, reB0 * sB0);
            di0 = fmaf(imA0, sA0, imB0 * sB0);
        }
        if (px1) {
            float sAf = __shfl_xor_sync(0xffffffffu, sB1, 31);
            float sBf = __shfl_xor_sync(0xffffffffu, sA1, 31);
            dr1 = fmaf(reA1, sAf, reB1 * sBf);
            di1 = fmaf(imA1, sAf, imB1 * sBf);
        } else {
            dr1 = fmaf(reA1, sA1, reB1 * sB1);
            di1 = fmaf(imA1, sA1, imB1 * sB1);
        }
        #pragma unroll
        for (int o = 16; o > 0; o >>= 1) {
            dr0 += __shfl_xor_sync(0xffffffffu, dr0, o);
            di0 += __shfl_xor_sync(0xffffffffu, di0, o);
            dr1 += __shfl_xor_sync(0xffffffffu, dr1, o);
            di1 += __shfl_xor_sync(0xffffffffu, di1, o);
        }

        float nn0  = sqrtf(ns0) + 1e-8f;
        float nn1  = sqrtf(ns1) + 1e-8f;
        float inv0 = __fdividef(1.f, nn0);
        float inv1 = __fdividef(1.f, nn1);
        float fid0 = s_es[q]     * sqrtf(fmaf(dr0, dr0, di0 * di0)) * inv0;
        float fid1 = s_es[q + 1] * sqrtf(fmaf(dr1, dr1, di1 * di1)) * inv1;
        bool flip0 = px0 != (fid0 < 0.9f);           // warp-uniform
        bool flip1 = px1 != (fid1 < 0.9f);

        float mA0 = fabsf(gsA0), mB0 = fabsf(gsB0);
        float mA1 = fabsf(gsA1), mB1 = fabsf(gsB1);
        float oA0, oB0, oA1, oB1;
        if (flip0) {
            oA0 = __shfl_xor_sync(0xffffffffu, mB0, 31);
            oB0 = __shfl_xor_sync(0xffffffffu, mA0, 31);
        } else { oA0 = mA0; oB0 = mB0; }
        if (flip1) {
            oA1 = __shfl_xor_sync(0xffffffffu, mB1, 31);
            oB1 = __shfl_xor_sync(0xffffffffu, mA1, 31);
        } else { oA1 = mA1; oB1 = mB1; }

        orow2[q * 32 + lane]       = make_float2(oA0 * inv0, oB0 * inv0);
        orow2[(q + 1) * 32 + lane] = make_float2(oA1 * inv1, oB1 * inv1);
    }
}

extern "C" void kernel_launch(void* const* d_in, const int* in_sizes, int n_in,
                              void* d_out, int out_size) {
    const float* x   = (const float*)d_in[0];
    const float* rx  = (const float*)d_in[1];
    const float* ry  = (const float*)d_in[2];
    const float* rz  = (const float*)d_in[3];
    const float* ecc = (const float*)d_in[4];
    const float* syn = (const float*)d_in[5];
    float* out = (float*)d_out;

    qsetup<<<1, 256>>>(rx, ry, rz, ecc, syn);
    qmain<<<4096 * 2, 128>>>(x, out);  // block = (row, q-half); ~6.9 waves
}

// round 17
// speedup vs baseline: 1.1066x; 1.0537x over previous
#include <cuda_runtime.h>
#include <cstdint>

// ====================================================================
// QuantumLayer: 3x (fft2,diag(q),ifft2) == ONE real 32-tap circulant
// along q; pz dead; out[q][d] = |noisy| at d or 63-d,
// flip = px ^ (fid < 0.9). JAX threefry (partitionable) on device.
// R16: R15 + paired-tap float2 table (-32 LDS/q-pair), folded sqrt2
//      noise scales (-8 FMUL/q-pair), shuffle-based qsetup blkred
//      (3 barriers instead of 8).
// ====================================================================

static __device__ float        g_ck[32];    // composed circulant kernel
static __device__ float        g_esum[32];  // |sum_a ecc[a][q]|
static __device__ float        g_syn0[32];  // syn[0][q]
static __device__ unsigned int g_keys[4];   // k1 (amp), k2 (phase)

// ---------------- threefry2x32 ----------------
__device__ __forceinline__ unsigned int rotl32(unsigned int x, int r) {
    return __funnelshift_l(x, x, r);
}

__device__ __forceinline__ void tf2x32(unsigned int k0, unsigned int k1,
                                       unsigned int x0, unsigned int x1,
                                       unsigned int& o0, unsigned int& o1) {
    unsigned int k2 = k0 ^ k1 ^ 0x1BD11BDAu;
    x0 += k0; x1 += k1;
#define TFR4(a,b,c,d) \
    x0 += x1; x1 = rotl32(x1,(a)) ^ x0; \
    x0 += x1; x1 = rotl32(x1,(b)) ^ x0; \
    x0 += x1; x1 = rotl32(x1,(c)) ^ x0; \
    x0 += x1; x1 = rotl32(x1,(d)) ^ x0;
    TFR4(13,15,26, 6)  x0 += k1; x1 += k2 + 1u;
    TFR4(17,29,16,24)  x0 += k2; x1 += k0 + 2u;
    TFR4(13,15,26, 6)  x0 += k0; x1 += k1 + 3u;
    TFR4(17,29,16,24)  x0 += k1; x1 += k2 + 4u;
    TFR4(13,15,26, 6)  x0 += k2; x1 += k0 + 5u;
#undef TFR4
    o0 = x0; o1 = x1;
}

// partitionable random_bits: counter = (hi=0, lo=idx), fold the two outputs
__device__ __forceinline__ unsigned int tf_fold(unsigned int k0, unsigned int k1,
                                                unsigned int idx) {
    unsigned int o0, o1;
    tf2x32(k0, k1, 0u, idx, o0, o1);
    return o0 ^ o1;
}

// bits -> erfinv(u), u matching jax.random.normal f32 path (sqrt2 folded
// into the caller's scale constants)
__device__ __forceinline__ float einv_from_bits(unsigned int bits) {
    float f = __uint_as_float(0x3f800000u | (bits >> 9)) - 1.0f; // [0,1)
    const float LO = -0.99999994f;          // nextafter(-1,0) in f32
    float u = fmaxf(LO, fmaf(f, 2.0f, LO)); // (1 - LO) rounds to exactly 2.0f
    return erfinvf(u);
}

// 0.01*sqrt(2), 0.005*sqrt(2)
#define C_AMP 0.0141421356f
#define C_PH  0.0070710678f

// ---------------- setup: QR -> thetas -> circulant, keys, scalars ----
__global__ void qsetup(const float* __restrict__ rx, const float* __restrict__ ry,
                       const float* __restrict__ rz, const float* __restrict__ ecc,
                       const float* __restrict__ syn) {
    __shared__ double sA0[256], sA1[256], sV[256], sW[256], sT2[256];
    __shared__ double red[8];
    __shared__ double sTh[3][32];
    __shared__ double sCax[3][32], sT12[32];
    __shared__ double cw[32], sw[32];
    __shared__ double dreS[3][32], dimS[3][32];
    __shared__ double sc_tau, sc_sc, sc_tau2, sc_sc2, sc_tva, sc_tvu;

    const int tid = threadIdx.x;
    const float* ps[3] = { rx, ry, rz };

    // block reduction: warp butterfly + 8-partial butterfly (3 barriers)
    auto blkred = [&](double v) -> double {
        #pragma unroll
        for (int o = 16; o > 0; o >>= 1)
            v += __shfl_xor_sync(0xffffffffu, v, o);
        if ((tid & 31) == 0) red[tid >> 5] = v;
        __syncthreads();
        if (tid < 32) {
            double r2 = (tid < 8) ? red[tid] : 0.0;
            #pragma unroll
            for (int o = 4; o > 0; o >>= 1)
                r2 += __shfl_xor_sync(0xffffffffu, r2, o);
            if (tid == 0) red[0] = r2;
        }
        __syncthreads();
        double r = red[0];
        __syncthreads();
        return r;
    };

    for (int a = 0; a < 3; ++a) {
        const float* p = ps[a];
        sA0[tid] = (double)p[2*tid];
        sA1[tid] = (double)p[2*tid + 1];
        __syncthreads();

        double na = sqrt(blkred(sA0[tid] * sA0[tid]));
        if (tid == 0) {
            double alpha = sA0[0];
            double beta  = (alpha >= 0.0) ? -na : na;     // LAPACK slarfg sign
            sc_tau = (beta - alpha) / beta;
            sc_sc  = 1.0 / (alpha - beta);
        }
        __syncthreads();
        sV[tid] = (tid == 0) ? 1.0 : sA0[tid] * sc_sc;
        __syncthreads();

        double va = blkred(sV[tid] * sA1[tid]);
        if (tid == 0) sc_tva = sc_tau * va;
        __syncthreads();
        sW[tid] = sA1[tid] - sc_tva * sV[tid];
        __syncthreads();

        double nz = sqrt(blkred((tid >= 1) ? sW[tid] * sW[tid] : 0.0));
        if (tid == 0) {
            double alpha2 = sW[1];
            double beta2  = (alpha2 >= 0.0) ? -nz : nz;
            sc_tau2 = (beta2 - alpha2) / beta2;
            sc_sc2  = 1.0 / (alpha2 - beta2);
        }
        __syncthreads();
        {
            double u = (tid == 0) ? 0.0 : ((tid == 1) ? 1.0 : sW[tid] * sc_sc2);
            sT2[tid] = ((tid == 1) ? 1.0 : 0.0) - sc_tau2 * u;
        }
        __syncthreads();

        double vu = blkred(sV[tid] * sT2[tid]);
        if (tid == 0) sc_tvu = sc_tau * vu;
        __syncthreads();

        if (tid < 32) {
            double t = 0.0;
            for (int i = 8*tid; i < 8*tid + 8; ++i) {
                double q0 = ((i == 0) ? 1.0 : 0.0) - sc_tau * sV[i];    // Q col 0
                double q1 = sT2[i] - sc_tvu * sV[i];                    // Q col 1
                t += q0 + q1;
            }
            sTh[a][tid] = t / 16.0;
        }
        __syncthreads();
    }

    // roots-of-unity tables + per-axis diag trig, all axes concurrent (96 thr)
    const double PI = 3.14159265358979323846;
    if (tid < 32) {
        double wv = (2.0 * PI / 32.0) * (double)tid;
        cw[tid] = cos(wv);
        sw[tid] = sin(wv);
    }
    if (tid < 96) {
        int a = tid >> 5, k = tid & 31;
        double ang = 0.5 * sTh[a][2*(k >> 1)];     // theta[0::2] repeated
        dreS[a][k] = cos(ang);
        dimS[a][k] = (a < 2) ? 0.0 : ((k & 1) ? sin(ang) : -sin(ang));
    }
    __syncthreads();

    // per-axis circulant kernels, all axes concurrent (96 threads)
    if (tid < 96) {
        int a = tid >> 5, j = tid & 31;
        double acc = 0.0;
        for (int k = 0; k < 32; ++k) {
            int w = (k * j) & 31;
            acc += dreS[a][k] * cw[w] - dimS[a][k] * sw[w];
        }
        sCax[a][j] = acc / 32.0;
    }
    __syncthreads();

    // compose: ct = cx (*) cy (*) cz (circular convolution)
    if (tid < 32) {
        double s3 = 0.0;
        for (int m = 0; m < 32; ++m) s3 += sCax[0][m] * sCax[1][(tid - m) & 31];
        sT12[tid] = s3;
    }
    __syncthreads();
    if (tid < 32) {
        double s3 = 0.0;
        for (int m = 0; m < 32; ++m) s3 += sT12[m] * sCax[2][(tid - m) & 31];
        g_ck[tid] = (float)s3;
        g_esum[tid] = fabsf(ecc[tid] + ecc[32 + tid] + ecc[64 + tid]);
        g_syn0[tid] = syn[tid];
    }

    if (tid == 0) {
        unsigned int o0, o1;
        tf2x32(0u, 42u, 0u, 0u, o0, o1); g_keys[0] = o0; g_keys[1] = o1;
        tf2x32(0u, 42u, 0u, 1u, o0, o1); g_keys[2] = o0; g_keys[3] = o1;
    }
}

// ---------------- main: block = (row, q-half); warp w owns 4 q's -----
// 8192 blocks, 128 threads. Block bid: row = bid>>1, half = bid&1.
// Warp w owns q in [16*half + 4*w, 16*half + 4*w + 4).
__global__ __launch_bounds__(128, 9)
void qmain(const float* __restrict__ x, float* __restrict__ out) {
    __shared__ float2 xsh[32][32];       // [m][lane] = (x[m*64+2l], x[m*64+2l+1])
    __shared__ float2 s_ctp[64];         // s_ctp[t] = (ct[(t+1)&31], ct[(t+2)&31])
    __shared__ float  s_syn[32], s_es[32];
    __shared__ unsigned int s_keys[4];

    const int t = threadIdx.x;
    if (t < 64)               s_ctp[t] = make_float2(g_ck[(t + 1) & 31],
                                                     g_ck[(t + 2) & 31]);
    else if (t < 96)          s_syn[t - 64] = g_syn0[t - 64];
    else                      s_es[t - 96]  = g_esum[t - 96];
    if (t < 4)                s_keys[t]     = g_keys[t];

    const unsigned int row  = blockIdx.x >> 1;
    const int          half = blockIdx.x & 1;

    // load x row (8KB, float4 linear copy == float2[m][lane] layout)
    {
        const float4* xr4 = (const float4*)(x + (size_t)row * 2048);
        float4* xs4 = (float4*)&xsh[0][0];
        #pragma unroll
        for (int i = 0; i < 4; ++i)
            xs4[t + 128 * i] = xr4[t + 128 * i];
    }
    __syncthreads();                     // publishes xsh AND s_keys/tables

    const unsigned int K1a = s_keys[0], K1b = s_keys[1];
    const unsigned int K2a = s_keys[2], K2b = s_keys[3];

    const int warp = t >> 5, lane = t & 31;
    const int qb = half * 16 + warp * 4;             // this warp's 4 q's
    float2* orow2 = (float2*)(out + (size_t)row * 2048);
    const unsigned int idx0 = row * 2048u + 2u * (unsigned int)lane;

    #pragma unroll 1
    for (int qq = 0; qq < 4; qq += 2) {
        const int q = qb + qq;

        // circulant along q for q and q+1: paired taps, one LDS.64 per m
        const float2* cpp = s_ctp + q + 31;          // cpp[-m] = (ct[(q-m)&31], ct[(q+1-m)&31])
        float sA0 = 0.f, sB0 = 0.f, sA1 = 0.f, sB1 = 0.f;
        #pragma unroll
        for (int m = 0; m < 32; ++m) {
            float2 xm = xsh[m][lane];
            float2 cc = cpp[-m];
            sA0 = fmaf(cc.x, xm.x, sA0); sB0 = fmaf(cc.x, xm.y, sB0);
            sA1 = fmaf(cc.y, xm.x, sA1); sB1 = fmaf(cc.y, xm.y, sB1);
        }

        // 8 independent threefry chains (ILP)
        const unsigned int i0 = idx0 + (unsigned int)q * 64u;
        unsigned int bA0a = tf_fold(K1a, K1b, i0);
        unsigned int bA0p = tf_fold(K2a, K2b, i0);
        unsigned int bB0a = tf_fold(K1a, K1b, i0 + 1u);
        unsigned int bB0p = tf_fold(K2a, K2b, i0 + 1u);
        unsigned int bA1a = tf_fold(K1a, K1b, i0 + 64u);
        unsigned int bA1p = tf_fold(K2a, K2b, i0 + 64u);
        unsigned int bB1a = tf_fold(K1a, K1b, i0 + 65u);
        unsigned int bB1p = tf_fold(K2a, K2b, i0 + 65u);

        float ampA0 = C_AMP * einv_from_bits(bA0a);
        float phA0  = C_PH  * einv_from_bits(bA0p);
        float ampB0 = C_AMP * einv_from_bits(bB0a);
        float phB0  = C_PH  * einv_from_bits(bB0p);
        float ampA1 = C_AMP * einv_from_bits(bA1a);
        float phA1  = C_PH  * einv_from_bits(bA1p);
        float ampB1 = C_AMP * einv_from_bits(bB1a);
        float phB1  = C_PH  * einv_from_bits(bB1p);

        float gsA0 = fmaf(ampA0, sA0, sA0), gsB0 = fmaf(ampB0, sB0, sB0);
        float gsA1 = fmaf(ampA1, sA1, sA1), gsB1 = fmaf(ampB1, sB1, sB1);

        // small-angle sincos: |ph| <= 0.027 => err < 3e-8
        float pA0 = phA0 * phA0, pB0 = phB0 * phB0;
        float pA1 = phA1 * phA1, pB1 = phB1 * phB1;
        float cA0 = fmaf(-0.5f, pA0, 1.f), snA0 = phA0 * fmaf(-0.16666667f, pA0, 1.f);
        float cB0 = fmaf(-0.5f, pB0, 1.f), snB0 = phB0 * fmaf(-0.16666667f, pB0, 1.f);
        float cA1 = fmaf(-0.5f, pA1, 1.f), snA1 = phA1 * fmaf(-0.16666667f, pA1, 1.f);
        float cB1 = fmaf(-0.5f, pB1, 1.f), snB1 = phB1 * fmaf(-0.16666667f, pB1, 1.f);

        float reA0 = gsA0 * cA0, imA0 = gsA0 * snA0;
        float reB0 = gsB0 * cB0, imB0 = gsB0 * snB0;
        float reA1 = gsA1 * cA1, imA1 = gsA1 * snA1;
        float reB1 = gsB1 * cB1, imB1 = gsB1 * snB1;

        // phase 1: norm^2 and Re-sum for both q (interleaved butterflies)
        float ns0  = fmaf(gsA0, gsA0, gsB0 * gsB0);
        float ns1  = fmaf(gsA1, gsA1, gsB1 * gsB1);
        float sre0 = reA0 + reB0;
        float sre1 = reA1 + reB1;
        #pragma unroll
        for (int o = 16; o > 0; o >>= 1) {
            ns0  += __shfl_xor_sync(0xffffffffu, ns0,  o);
            ns1  += __shfl_xor_sync(0xffffffffu, ns1,  o);
            sre0 += __shfl_xor_sync(0xffffffffu, sre0, o);
            sre1 += __shfl_xor_sync(0xffffffffu, sre1, o);
        }
        bool px0 = (s_syn[q]     * sre0) > 0.f;      // warp-uniform
        bool px1 = (s_syn[q + 1] * sre1) > 0.f;

        // phase 2: selected dot only (flip partner d<->63-d: lane^31, slot swap)
        float dr0, di0, dr1, di1;
        if (px0) {
            float sAf = __shfl_xor_sync(0xffffffffu, sB0, 31);
            float sBf = __shfl_xor_sync(0xffffffffu, sA0, 31);
            dr0 = fmaf(reA0, sAf, reB0 * sBf);
            di0 = fmaf(imA0, sAf, imB0 * sBf);
        } else {
            dr0 = fmaf(reA0, sA0, reB0 * sB0);
            di0 = fmaf(imA0, sA0, imB0 * sB0);
        }
        if (px1) {
            float sAf = __shfl_xor_sync(0xffffffffu, sB1, 31);
            float sBf = __shfl_xor_sync(0xffffffffu, sA1, 31);
            dr1 = fmaf(reA1, sAf, reB1 * sBf);
            di1 = fmaf(imA1, sAf, imB1 * sBf);
        } else {
            dr1 = fmaf(reA1, sA1, reB1 * sB1);
            di1 = fmaf(imA1, sA1, imB1 * sB1);
        }
        #pragma unroll
        for (int o = 16; o > 0; o >>= 1) {
            dr0 += __shfl_xor_sync(0xffffffffu, dr0, o);
            di0 += __shfl_xor_sync(0xffffffffu, di0, o);
            dr1 += __shfl_xor_sync(0xffffffffu, dr1, o);
            di1 += __shfl_xor_sync(0xffffffffu, di1, o);
        }

        float nn0  = sqrtf(ns0) + 1e-8f;
        float nn1  = sqrtf(ns1) + 1e-8f;
        float inv0 = __fdividef(1.f, nn0);
        float inv1 = __fdividef(1.f, nn1);
        float fid0 = s_es[q]     * sqrtf(fmaf(dr0, dr0, di0 * di0)) * inv0;
        float fid1 = s_es[q + 1] * sqrtf(fmaf(dr1, dr1, di1 * di1)) * inv1;
        bool flip0 = px0 != (fid0 < 0.9f);           // warp-uniform
        bool flip1 = px1 != (fid1 < 0.9f);

        float mA0 = fabsf(gsA0), mB0 = fabsf(gsB0);
        float mA1 = fabsf(gsA1), mB1 = fabsf(gsB1);
        float oA0, oB0, oA1, oB1;
        if (flip0) {
            oA0 = __shfl_xor_sync(0xffffffffu, mB0, 31);
            oB0 = __shfl_xor_sync(0xffffffffu, mA0, 31);
        } else { oA0 = mA0; oB0 = mB0; }
        if (flip1) {
            oA1 = __shfl_xor_sync(0xffffffffu, mB1, 31);
            oB1 = __shfl_xor_sync(0xffffffffu, mA1, 31);
        } else { oA1 = mA1; oB1 = mB1; }

        orow2[q * 32 + lane]       = make_float2(oA0 * inv0, oB0 * inv0);
        orow2[(q + 1) * 32 + lane] = make_float2(oA1 * inv1, oB1 * inv1);
    }
}

extern "C" void kernel_launch(void* const* d_in, const int* in_sizes, int n_in,
                              void* d_out, int out_size) {
    const float* x   = (const float*)d_in[0];
    const float* rx  = (const float*)d_in[1];
    const float* ry  = (const float*)d_in[2];
    const float* rz  = (const float*)d_in[3];
    const float* ecc = (const float*)d_in[4];
    const float* syn = (const float*)d_in[5];
    float* out = (float*)d_out;

    qsetup<<<1, 256>>>(rx, ry, rz, ecc, syn);
    qmain<<<4096 * 2, 128>>>(x, out);  // block = (row, q-half); ~6.9 waves
}